// round 2
// baseline (speedup 1.0000x reference)
#include <cuda_runtime.h>
#include <cstdint>
#include <cstddef>

// Problem constants
#define BB   4096
#define TT   24
#define II   128
#define HH   512
#define WW   32
#define BT   (BB*TT)   // 98304

// Scratch (static device arrays; allocation-free per harness rules)
__device__ float g_E [(size_t)BT*HH];   // sigmoid(weather proj)
__device__ float g_po[(size_t)BT*HH];
__device__ float g_pr[(size_t)BT*HH];
__device__ float g_pz[(size_t)BT*HH];
__device__ float g_ph[(size_t)BT*HH];

__device__ __forceinline__ float sigmoidf_(float x) {
    return 1.0f / (1.0f + __expf(-x));
}

// static component select (folds under full unroll)
#define GETC(v, c) ((c)==0 ? (v).x : (c)==1 ? (v).y : (c)==2 ? (v).z : (v).w)

// ============================================================================
// Kernel 1: E = sigmoid(XW[BT,32] @ w_e[512,32]^T + b_e)
// Block: 64 rows x 128 cols, 256 threads, K=32 single tile. (small; ~2% of time)
// ============================================================================
__global__ __launch_bounds__(256)
void e_kernel(const float* __restrict__ xw, const float* __restrict__ w_e,
              const float* __restrict__ b_e) {
    __shared__ float As[32][68];    // [k][m]
    __shared__ float Ws[32][132];   // [k][n]
    const int r0 = blockIdx.x * 64;
    const int c0 = blockIdx.y * 128;
    const int tid = threadIdx.x;

    #pragma unroll
    for (int p = 0; p < 2; p++) {
        int idx = tid + p * 256;            // < 512 = 64*8
        int m = idx >> 3, kq = idx & 7;
        float4 v = *(const float4*)(xw + (size_t)(r0 + m) * WW + kq * 4);
        As[kq*4+0][m] = v.x; As[kq*4+1][m] = v.y;
        As[kq*4+2][m] = v.z; As[kq*4+3][m] = v.w;
    }
    #pragma unroll
    for (int p = 0; p < 4; p++) {
        int idx = tid + p * 256;            // < 1024 = 128*8
        int n = idx >> 3, kq = idx & 7;
        float4 v = *(const float4*)(w_e + (size_t)(c0 + n) * WW + kq * 4);
        Ws[kq*4+0][n] = v.x; Ws[kq*4+1][n] = v.y;
        Ws[kq*4+2][n] = v.z; Ws[kq*4+3][n] = v.w;
    }
    __syncthreads();

    const int tm = tid >> 4, tn = tid & 15;   // 16 x 16 thread grid
    float acc[4][8];
    #pragma unroll
    for (int i = 0; i < 4; i++)
        #pragma unroll
        for (int j = 0; j < 8; j++) acc[i][j] = 0.f;

    #pragma unroll 4
    for (int kk = 0; kk < 32; kk++) {
        float a[4], b[8];
        #pragma unroll
        for (int i = 0; i < 4; i++) a[i] = As[kk][tm + 16*i];
        #pragma unroll
        for (int j = 0; j < 8; j++) b[j] = Ws[kk][tn + 16*j];
        #pragma unroll
        for (int i = 0; i < 4; i++)
            #pragma unroll
            for (int j = 0; j < 8; j++) acc[i][j] += a[i] * b[j];
    }

    #pragma unroll
    for (int i = 0; i < 4; i++) {
        int m = r0 + tm + 16*i;
        #pragma unroll
        for (int j = 0; j < 8; j++) {
            int n = c0 + tn + 16*j;
            g_E[(size_t)m * HH + n] = sigmoidf_(acc[i][j] + b_e[n]);
        }
    }
}

// ============================================================================
// Kernel 2: all pre-activations. blockIdx.z selects target:
//   0: pre_h = X@w_hx^T + b_h
//   1: pre_r = X@w_rx^T + E@w_re^T + b_r
//   2: pre_z = X@w_zx^T + E@w_ze^T + b_z
//   3: pre_o = Xs24@w_d^T + Xs168@w_w^T + Xs720@w_m^T   (row-shifted X)
// Block: 128 rows x 128 cols, 256 threads (16x16), 8x8 per-thread tile,
// all smem operand fetch via LDS.128 (A stored [m][k], padded stride 36).
// ============================================================================
#define LDA_PRE 36   // 36*4B = 144B, 16B multiple -> float4-aligned rows

__global__ __launch_bounds__(256)
void pre_kernel(const float* __restrict__ X,
                const float* __restrict__ w_rx, const float* __restrict__ w_re,
                const float* __restrict__ b_r,
                const float* __restrict__ w_zx, const float* __restrict__ w_ze,
                const float* __restrict__ b_z,
                const float* __restrict__ w_hx, const float* __restrict__ b_h,
                const float* __restrict__ w_d,  const float* __restrict__ w_w,
                const float* __restrict__ w_m) {
    __shared__ float As[128 * LDA_PRE];   // [m][k], 18432 B
    __shared__ float Ws[32][132];         // [k][n], 16896 B
    const int r0 = blockIdx.x * 128;
    const int c0 = blockIdx.y * 128;
    const int tid = threadIdx.x;

    const float* Ap[3]; const float* Wp[3];
    int Ks[3], Ld[3], Sh[3], nseg;
    const float* bias; float* dst;
    switch (blockIdx.z) {
        case 0: nseg = 1;
            Ap[0]=X;   Wp[0]=w_hx; Ks[0]=II; Ld[0]=II; Sh[0]=0;
            bias = b_h; dst = g_ph; break;
        case 1: nseg = 2;
            Ap[0]=X;   Wp[0]=w_rx; Ks[0]=II; Ld[0]=II; Sh[0]=0;
            Ap[1]=g_E; Wp[1]=w_re; Ks[1]=HH; Ld[1]=HH; Sh[1]=0;
            bias = b_r; dst = g_pr; break;
        case 2: nseg = 2;
            Ap[0]=X;   Wp[0]=w_zx; Ks[0]=II; Ld[0]=II; Sh[0]=0;
            Ap[1]=g_E; Wp[1]=w_ze; Ks[1]=HH; Ld[1]=HH; Sh[1]=0;
            bias = b_z; dst = g_pz; break;
        default: nseg = 3;
            Ap[0]=X; Wp[0]=w_d; Ks[0]=II; Ld[0]=II; Sh[0]=24;
            Ap[1]=X; Wp[1]=w_w; Ks[1]=II; Ld[1]=II; Sh[1]=168;
            Ap[2]=X; Wp[2]=w_m; Ks[2]=II; Ld[2]=II; Sh[2]=720;
            bias = nullptr; dst = g_po; break;
    }

    const int tm = tid >> 4;        // 0..15 -> rows tm + 16*i
    const int tn = tid & 15;        // 0..15 -> cols tn*4 + 64*j (float4 groups)
    float acc[8][2][4];
    #pragma unroll
    for (int i = 0; i < 8; i++)
        #pragma unroll
        for (int j = 0; j < 2; j++)
            #pragma unroll
            for (int c = 0; c < 4; c++) acc[i][j][c] = 0.f;

    for (int s = 0; s < nseg; s++) {
        const float* A  = Ap[s];
        const float* Wt = Wp[s];
        const int K = Ks[s], lda = Ld[s], shift = Sh[s];
        for (int kt = 0; kt < K; kt += 32) {
            // A tile [128 rows x 32 k] -> As[m][k], direct float4 stores
            #pragma unroll
            for (int p = 0; p < 4; p++) {
                int idx = tid + p * 256;        // < 1024
                int m = idx >> 3, kq = idx & 7;
                int gr = r0 + m - shift;
                float4 v = make_float4(0.f, 0.f, 0.f, 0.f);
                if (gr >= 0)
                    v = *(const float4*)(A + (size_t)gr * lda + kt + kq * 4);
                *(float4*)&As[m * LDA_PRE + kq * 4] = v;
            }
            // W tile [128 n x 32 k] -> Ws[k][n] (transpose)
            #pragma unroll
            for (int p = 0; p < 4; p++) {
                int idx = tid + p * 256;
                int n = idx >> 3, kq = idx & 7;
                float4 v = *(const float4*)(Wt + (size_t)(c0 + n) * K + kt + kq * 4);
                Ws[kq*4+0][n] = v.x; Ws[kq*4+1][n] = v.y;
                Ws[kq*4+2][n] = v.z; Ws[kq*4+3][n] = v.w;
            }
            __syncthreads();

            #pragma unroll
            for (int k4 = 0; k4 < 8; k4++) {
                float4 a4[8];
                #pragma unroll
                for (int i = 0; i < 8; i++)
                    a4[i] = *(const float4*)&As[(tm + 16*i) * LDA_PRE + k4 * 4];
                #pragma unroll
                for (int kk = 0; kk < 4; kk++) {
                    const float* wrow = &Ws[k4*4 + kk][tn * 4];
                    float4 b0 = *(const float4*)(wrow);
                    float4 b1 = *(const float4*)(wrow + 64);
                    #pragma unroll
                    for (int i = 0; i < 8; i++) {
                        float av = GETC(a4[i], kk);
                        acc[i][0][0] += av * b0.x; acc[i][0][1] += av * b0.y;
                        acc[i][0][2] += av * b0.z; acc[i][0][3] += av * b0.w;
                        acc[i][1][0] += av * b1.x; acc[i][1][1] += av * b1.y;
                        acc[i][1][2] += av * b1.z; acc[i][1][3] += av * b1.w;
                    }
                }
            }
            __syncthreads();
        }
    }

    #pragma unroll
    for (int i = 0; i < 8; i++) {
        int m = r0 + tm + 16*i;
        #pragma unroll
        for (int j = 0; j < 2; j++) {
            int n = c0 + tn * 4 + j * 64;
            float4 bs = make_float4(0.f, 0.f, 0.f, 0.f);
            if (bias) bs = *(const float4*)&bias[n];
            float4 v;
            v.x = acc[i][j][0] + bs.x; v.y = acc[i][j][1] + bs.y;
            v.z = acc[i][j][2] + bs.z; v.w = acc[i][j][3] + bs.w;
            *(float4*)&dst[(size_t)m * HH + n] = v;
        }
    }
}

// ============================================================================
// Kernel 3: recurrence. Persistent blocks: 128 blocks x 32 batch rows.
// h kept in SMEM; per step 4 GEMMs [32x512]x[512x512]^T with weight tiles
// double-buffered through registers into SMEM. All operand fetch LDS.128.
// SMEM: bufA[32*516] + bufB[32*516] + ws[16*516]  = 165120 B
// ============================================================================
#define LDH 516   // 516*4B = 2064B, 16B multiple
#define REC_SMEM ((2*32*LDH + 16*LDH) * 4)

__device__ __forceinline__ void mm32x512(const float* sb, const float* __restrict__ Wg,
                                         float* ws, float (&acc)[8][2][4],
                                         int tid, int tm, int tn) {
    #pragma unroll
    for (int i = 0; i < 8; i++)
        #pragma unroll
        for (int j = 0; j < 2; j++)
            #pragma unroll
            for (int c = 0; c < 4; c++) acc[i][j][c] = 0.f;

    float4 pf[8];
    #pragma unroll
    for (int p = 0; p < 8; p++) {
        int idx = tid + p * 256;            // < 2048
        int kq = idx & 3, n = idx >> 2;     // n < 512
        pf[p] = *(const float4*)(Wg + (size_t)n * HH + kq * 4);
    }
    #pragma unroll 1
    for (int kt = 0; kt < 32; kt++) {       // 32 tiles of K=16
        __syncthreads();                    // previous consumers done with ws
        #pragma unroll
        for (int p = 0; p < 8; p++) {
            int idx = tid + p * 256;
            int kq = idx & 3, n = idx >> 2;
            ws[(kq*4+0)*LDH + n] = pf[p].x;
            ws[(kq*4+1)*LDH + n] = pf[p].y;
            ws[(kq*4+2)*LDH + n] = pf[p].z;
            ws[(kq*4+3)*LDH + n] = pf[p].w;
        }
        __syncthreads();
        if (kt < 31) {
            #pragma unroll
            for (int p = 0; p < 8; p++) {
                int idx = tid + p * 256;
                int kq = idx & 3, n = idx >> 2;
                pf[p] = *(const float4*)(Wg + (size_t)n * HH + (kt + 1) * 16 + kq * 4);
            }
        }
        #pragma unroll
        for (int k4 = 0; k4 < 4; k4++) {
            float4 a4[8];
            #pragma unroll
            for (int i = 0; i < 8; i++)
                a4[i] = *(const float4*)(sb + (tm + 4*i) * LDH + kt * 16 + k4 * 4);
            #pragma unroll
            for (int kk = 0; kk < 4; kk++) {
                const float* wrow = ws + (k4*4 + kk) * LDH + tn * 4;
                float4 b0 = *(const float4*)(wrow);
                float4 b1 = *(const float4*)(wrow + 256);
                #pragma unroll
                for (int i = 0; i < 8; i++) {
                    float av = GETC(a4[i], kk);
                    acc[i][0][0] += av * b0.x; acc[i][0][1] += av * b0.y;
                    acc[i][0][2] += av * b0.z; acc[i][0][3] += av * b0.w;
                    acc[i][1][0] += av * b1.x; acc[i][1][1] += av * b1.y;
                    acc[i][1][2] += av * b1.z; acc[i][1][3] += av * b1.w;
                }
            }
        }
    }
}

__global__ __launch_bounds__(256)
void rec_kernel(const float* __restrict__ w_t,  const float* __restrict__ w_rh,
                const float* __restrict__ w_zh, const float* __restrict__ w_hh,
                float* __restrict__ out) {
    extern __shared__ float smem[];
    float* bufA = smem;                 // h_t / rh / h_next
    float* bufB = smem + 32 * LDH;      // h_o
    float* ws   = smem + 64 * LDH;      // weight tile [16][516]

    const int rb0 = blockIdx.x * 32;    // batch rows owned by this block
    const int tid = threadIdx.x;
    const int tn = tid & 63, tm = tid >> 6;   // cols tn*4 + 256*j ; rows tm + 4*i

    for (int idx = tid; idx < 32 * LDH; idx += 256) bufA[idx] = 0.f;
    __syncthreads();

    float acc[8][2][4], zreg[8][2][4];

    for (int t = 0; t < TT; t++) {
        // ---- stage 1: h_o = sigmoid(pre_o + h @ w_t^T) -> bufB ----
        mm32x512(bufA, w_t, ws, acc, tid, tm, tn);
        #pragma unroll
        for (int i = 0; i < 8; i++) {
            int m = tm + 4*i;
            size_t prow = ((size_t)(rb0 + m) * TT + t) * HH;
            #pragma unroll
            for (int j = 0; j < 2; j++) {
                int n = tn * 4 + j * 256;
                float4 po = *(const float4*)&g_po[prow + n];
                float4 hv;
                hv.x = sigmoidf_(acc[i][j][0] + po.x);
                hv.y = sigmoidf_(acc[i][j][1] + po.y);
                hv.z = sigmoidf_(acc[i][j][2] + po.z);
                hv.w = sigmoidf_(acc[i][j][3] + po.w);
                *(float4*)&bufB[m * LDH + n] = hv;
            }
        }
        // (sync at top of next mm32x512 protects bufB)

        // ---- stage 2a: r = sigmoid(pre_r + h_o @ w_rh^T); bufA = r * h_o ----
        mm32x512(bufB, w_rh, ws, acc, tid, tm, tn);
        #pragma unroll
        for (int i = 0; i < 8; i++) {
            int m = tm + 4*i;
            size_t prow = ((size_t)(rb0 + m) * TT + t) * HH;
            #pragma unroll
            for (int j = 0; j < 2; j++) {
                int n = tn * 4 + j * 256;
                float4 pr = *(const float4*)&g_pr[prow + n];
                float4 ho = *(const float4*)&bufB[m * LDH + n];
                float4 rv;
                rv.x = sigmoidf_(acc[i][j][0] + pr.x) * ho.x;
                rv.y = sigmoidf_(acc[i][j][1] + pr.y) * ho.y;
                rv.z = sigmoidf_(acc[i][j][2] + pr.z) * ho.z;
                rv.w = sigmoidf_(acc[i][j][3] + pr.w) * ho.w;
                *(float4*)&bufA[m * LDH + n] = rv;
            }
        }

        // ---- stage 2b: z = sigmoid(pre_z + h_o @ w_zh^T), kept in regs ----
        mm32x512(bufB, w_zh, ws, zreg, tid, tm, tn);
        #pragma unroll
        for (int i = 0; i < 8; i++) {
            int m = tm + 4*i;
            size_t prow = ((size_t)(rb0 + m) * TT + t) * HH;
            #pragma unroll
            for (int j = 0; j < 2; j++) {
                int n = tn * 4 + j * 256;
                float4 pz = *(const float4*)&g_pz[prow + n];
                zreg[i][j][0] = sigmoidf_(zreg[i][j][0] + pz.x);
                zreg[i][j][1] = sigmoidf_(zreg[i][j][1] + pz.y);
                zreg[i][j][2] = sigmoidf_(zreg[i][j][2] + pz.z);
                zreg[i][j][3] = sigmoidf_(zreg[i][j][3] + pz.w);
            }
        }

        // ---- stage 3: h~ = tanh(pre_h + (r*h_o) @ w_hh^T);
        //               h = (1-z)*h_o + z*h~ -> bufA, out ----
        mm32x512(bufA, w_hh, ws, acc, tid, tm, tn);
        __syncthreads();    // all readers of bufA (rh) done before overwrite
        #pragma unroll
        for (int i = 0; i < 8; i++) {
            int m = tm + 4*i;
            size_t prow = ((size_t)(rb0 + m) * TT + t) * HH;
            #pragma unroll
            for (int j = 0; j < 2; j++) {
                int n = tn * 4 + j * 256;
                float4 ph = *(const float4*)&g_ph[prow + n];
                float4 ho = *(const float4*)&bufB[m * LDH + n];
                float4 hn;
                float z0 = zreg[i][j][0], z1 = zreg[i][j][1];
                float z2 = zreg[i][j][2], z3 = zreg[i][j][3];
                hn.x = (1.f - z0) * ho.x + z0 * tanhf(acc[i][j][0] + ph.x);
                hn.y = (1.f - z1) * ho.y + z1 * tanhf(acc[i][j][1] + ph.y);
                hn.z = (1.f - z2) * ho.z + z2 * tanhf(acc[i][j][2] + ph.z);
                hn.w = (1.f - z3) * ho.w + z3 * tanhf(acc[i][j][3] + ph.w);
                *(float4*)&bufA[m * LDH + n] = hn;
                *(float4*)&out[prow + n] = hn;
            }
        }
        __syncthreads();    // bufA complete before next step's stage 1
    }
}

// ============================================================================
// Launch
// ============================================================================
extern "C" void kernel_launch(void* const* d_in, const int* in_sizes, int n_in,
                              void* d_out, int out_size) {
    const float* x_input   = (const float*)d_in[0];
    const float* x_weather = (const float*)d_in[1];
    const float* w_rx = (const float*)d_in[2];
    const float* w_rh = (const float*)d_in[3];
    const float* w_re = (const float*)d_in[4];
    const float* b_r  = (const float*)d_in[5];
    const float* w_zx = (const float*)d_in[6];
    const float* w_zh = (const float*)d_in[7];
    const float* w_ze = (const float*)d_in[8];
    const float* b_z  = (const float*)d_in[9];
    const float* w_hx = (const float*)d_in[10];
    const float* w_hh = (const float*)d_in[11];
    const float* b_h  = (const float*)d_in[12];
    const float* w_d  = (const float*)d_in[13];
    const float* w_w  = (const float*)d_in[14];
    const float* w_m  = (const float*)d_in[15];
    const float* w_t  = (const float*)d_in[16];
    const float* w_e  = (const float*)d_in[17];
    const float* b_e  = (const float*)d_in[18];
    float* out = (float*)d_out;

    cudaFuncSetAttribute(rec_kernel, cudaFuncAttributeMaxDynamicSharedMemorySize,
                         REC_SMEM);

    e_kernel<<<dim3(BT/64, HH/128, 1), 256>>>(x_weather, w_e, b_e);
    pre_kernel<<<dim3(BT/128, HH/128, 4), 256>>>(x_input,
                                                 w_rx, w_re, b_r,
                                                 w_zx, w_ze, b_z,
                                                 w_hx, b_h,
                                                 w_d, w_w, w_m);
    rec_kernel<<<BB/32, 256, REC_SMEM>>>(w_t, w_rh, w_zh, w_hh, out);
}

// round 3
// speedup vs baseline: 1.0047x; 1.0047x over previous
#include <cuda_runtime.h>
#include <cstdint>
#include <cstddef>

// Problem constants
#define BB   4096
#define TT   24
#define II   128
#define HH   512
#define WW   32
#define BT   (BB*TT)   // 98304

// Scratch (static device arrays; allocation-free per harness rules)
__device__ float g_E [(size_t)BT*HH];   // sigmoid(weather proj)
__device__ float g_po[(size_t)BT*HH];
__device__ float g_pr[(size_t)BT*HH];
__device__ float g_pz[(size_t)BT*HH];
__device__ float g_ph[(size_t)BT*HH];

__device__ __forceinline__ float sigmoidf_(float x) {
    return 1.0f / (1.0f + __expf(-x));
}

// static component select (folds under full unroll)
#define GETC(v, c) ((c)==0 ? (v).x : (c)==1 ? (v).y : (c)==2 ? (v).z : (v).w)

// ============================================================================
// Kernel 1: E = sigmoid(XW[BT,32] @ w_e[512,32]^T + b_e)
// Block: 64 rows x 128 cols, 256 threads, K=32 single tile. (small; ~2% of time)
// ============================================================================
__global__ __launch_bounds__(256)
void e_kernel(const float* __restrict__ xw, const float* __restrict__ w_e,
              const float* __restrict__ b_e) {
    __shared__ float As[32][68];    // [k][m]
    __shared__ float Ws[32][132];   // [k][n]
    const int r0 = blockIdx.x * 64;
    const int c0 = blockIdx.y * 128;
    const int tid = threadIdx.x;

    #pragma unroll
    for (int p = 0; p < 2; p++) {
        int idx = tid + p * 256;            // < 512 = 64*8
        int m = idx >> 3, kq = idx & 7;
        float4 v = *(const float4*)(xw + (size_t)(r0 + m) * WW + kq * 4);
        As[kq*4+0][m] = v.x; As[kq*4+1][m] = v.y;
        As[kq*4+2][m] = v.z; As[kq*4+3][m] = v.w;
    }
    #pragma unroll
    for (int p = 0; p < 4; p++) {
        int idx = tid + p * 256;            // < 1024 = 128*8
        int n = idx >> 3, kq = idx & 7;
        float4 v = *(const float4*)(w_e + (size_t)(c0 + n) * WW + kq * 4);
        Ws[kq*4+0][n] = v.x; Ws[kq*4+1][n] = v.y;
        Ws[kq*4+2][n] = v.z; Ws[kq*4+3][n] = v.w;
    }
    __syncthreads();

    const int tm = tid >> 4, tn = tid & 15;   // 16 x 16 thread grid
    float acc[4][8];
    #pragma unroll
    for (int i = 0; i < 4; i++)
        #pragma unroll
        for (int j = 0; j < 8; j++) acc[i][j] = 0.f;

    #pragma unroll 4
    for (int kk = 0; kk < 32; kk++) {
        float a[4], b[8];
        #pragma unroll
        for (int i = 0; i < 4; i++) a[i] = As[kk][tm + 16*i];
        #pragma unroll
        for (int j = 0; j < 8; j++) b[j] = Ws[kk][tn + 16*j];
        #pragma unroll
        for (int i = 0; i < 4; i++)
            #pragma unroll
            for (int j = 0; j < 8; j++) acc[i][j] += a[i] * b[j];
    }

    #pragma unroll
    for (int i = 0; i < 4; i++) {
        int m = r0 + tm + 16*i;
        #pragma unroll
        for (int j = 0; j < 8; j++) {
            int n = c0 + tn + 16*j;
            g_E[(size_t)m * HH + n] = sigmoidf_(acc[i][j] + b_e[n]);
        }
    }
}

// ============================================================================
// Kernel 2: all pre-activations. blockIdx.z selects target:
//   0: pre_h = X@w_hx^T + b_h
//   1: pre_r = X@w_rx^T + E@w_re^T + b_r
//   2: pre_z = X@w_zx^T + E@w_ze^T + b_z
//   3: pre_o = Xs24@w_d^T + Xs168@w_w^T + Xs720@w_m^T   (row-shifted X)
// Block: 128 rows x 128 cols, 256 threads (16x16), 8x8 per-thread tile,
// all smem operand fetch via LDS.128 (A stored [m][k], padded stride 36).
// ============================================================================
#define LDA_PRE 36   // 36*4B = 144B, 16B multiple -> float4-aligned rows

__global__ __launch_bounds__(256)
void pre_kernel(const float* __restrict__ X,
                const float* __restrict__ w_rx, const float* __restrict__ w_re,
                const float* __restrict__ b_r,
                const float* __restrict__ w_zx, const float* __restrict__ w_ze,
                const float* __restrict__ b_z,
                const float* __restrict__ w_hx, const float* __restrict__ b_h,
                const float* __restrict__ w_d,  const float* __restrict__ w_w,
                const float* __restrict__ w_m) {
    __shared__ float As[128 * LDA_PRE];   // [m][k], 18432 B
    __shared__ float Ws[32][132];         // [k][n], 16896 B
    const int r0 = blockIdx.x * 128;
    const int c0 = blockIdx.y * 128;
    const int tid = threadIdx.x;

    const float* Ap[3]; const float* Wp[3];
    int Ks[3], Ld[3], Sh[3], nseg;
    const float* bias; float* dst;
    switch (blockIdx.z) {
        case 0: nseg = 1;
            Ap[0]=X;   Wp[0]=w_hx; Ks[0]=II; Ld[0]=II; Sh[0]=0;
            bias = b_h; dst = g_ph; break;
        case 1: nseg = 2;
            Ap[0]=X;   Wp[0]=w_rx; Ks[0]=II; Ld[0]=II; Sh[0]=0;
            Ap[1]=g_E; Wp[1]=w_re; Ks[1]=HH; Ld[1]=HH; Sh[1]=0;
            bias = b_r; dst = g_pr; break;
        case 2: nseg = 2;
            Ap[0]=X;   Wp[0]=w_zx; Ks[0]=II; Ld[0]=II; Sh[0]=0;
            Ap[1]=g_E; Wp[1]=w_ze; Ks[1]=HH; Ld[1]=HH; Sh[1]=0;
            bias = b_z; dst = g_pz; break;
        default: nseg = 3;
            Ap[0]=X; Wp[0]=w_d; Ks[0]=II; Ld[0]=II; Sh[0]=24;
            Ap[1]=X; Wp[1]=w_w; Ks[1]=II; Ld[1]=II; Sh[1]=168;
            Ap[2]=X; Wp[2]=w_m; Ks[2]=II; Ld[2]=II; Sh[2]=720;
            bias = nullptr; dst = g_po; break;
    }

    const int tm = tid >> 4;        // 0..15 -> rows tm + 16*i
    const int tn = tid & 15;        // 0..15 -> cols tn*4 + 64*j (float4 groups)
    float acc[8][2][4];
    #pragma unroll
    for (int i = 0; i < 8; i++)
        #pragma unroll
        for (int j = 0; j < 2; j++)
            #pragma unroll
            for (int c = 0; c < 4; c++) acc[i][j][c] = 0.f;

    for (int s = 0; s < nseg; s++) {
        const float* A  = Ap[s];
        const float* Wt = Wp[s];
        const int K = Ks[s], lda = Ld[s], shift = Sh[s];
        for (int kt = 0; kt < K; kt += 32) {
            // A tile [128 rows x 32 k] -> As[m][k], direct float4 stores
            #pragma unroll
            for (int p = 0; p < 4; p++) {
                int idx = tid + p * 256;        // < 1024
                int m = idx >> 3, kq = idx & 7;
                int gr = r0 + m - shift;
                float4 v = make_float4(0.f, 0.f, 0.f, 0.f);
                if (gr >= 0)
                    v = *(const float4*)(A + (size_t)gr * lda + kt + kq * 4);
                *(float4*)&As[m * LDA_PRE + kq * 4] = v;
            }
            // W tile [128 n x 32 k] -> Ws[k][n] (transpose)
            #pragma unroll
            for (int p = 0; p < 4; p++) {
                int idx = tid + p * 256;
                int n = idx >> 3, kq = idx & 7;
                float4 v = *(const float4*)(Wt + (size_t)(c0 + n) * K + kt + kq * 4);
                Ws[kq*4+0][n] = v.x; Ws[kq*4+1][n] = v.y;
                Ws[kq*4+2][n] = v.z; Ws[kq*4+3][n] = v.w;
            }
            __syncthreads();

            #pragma unroll
            for (int k4 = 0; k4 < 8; k4++) {
                float4 a4[8];
                #pragma unroll
                for (int i = 0; i < 8; i++)
                    a4[i] = *(const float4*)&As[(tm + 16*i) * LDA_PRE + k4 * 4];
                #pragma unroll
                for (int kk = 0; kk < 4; kk++) {
                    const float* wrow = &Ws[k4*4 + kk][tn * 4];
                    float4 b0 = *(const float4*)(wrow);
                    float4 b1 = *(const float4*)(wrow + 64);
                    #pragma unroll
                    for (int i = 0; i < 8; i++) {
                        float av = GETC(a4[i], kk);
                        acc[i][0][0] += av * b0.x; acc[i][0][1] += av * b0.y;
                        acc[i][0][2] += av * b0.z; acc[i][0][3] += av * b0.w;
                        acc[i][1][0] += av * b1.x; acc[i][1][1] += av * b1.y;
                        acc[i][1][2] += av * b1.z; acc[i][1][3] += av * b1.w;
                    }
                }
            }
            __syncthreads();
        }
    }

    #pragma unroll
    for (int i = 0; i < 8; i++) {
        int m = r0 + tm + 16*i;
        #pragma unroll
        for (int j = 0; j < 2; j++) {
            int n = c0 + tn * 4 + j * 64;
            float4 bs = make_float4(0.f, 0.f, 0.f, 0.f);
            if (bias) bs = *(const float4*)&bias[n];
            float4 v;
            v.x = acc[i][j][0] + bs.x; v.y = acc[i][j][1] + bs.y;
            v.z = acc[i][j][2] + bs.z; v.w = acc[i][j][3] + bs.w;
            *(float4*)&dst[(size_t)m * HH + n] = v;
        }
    }
}

// ============================================================================
// Kernel 3: recurrence. Persistent blocks: 128 blocks x 32 batch rows.
// h kept in SMEM; per step 4 GEMMs [32x512]x[512x512]^T with weight tiles
// double-buffered through registers into SMEM. All operand fetch LDS.128.
// SMEM: bufA[32*516] + bufB[32*516] + ws[16*516]  = 165120 B
// ============================================================================
#define LDH 516   // 516*4B = 2064B, 16B multiple
#define REC_SMEM ((2*32*LDH + 16*LDH) * 4)

__device__ __forceinline__ void mm32x512(const float* sb, const float* __restrict__ Wg,
                                         float* ws, float (&acc)[8][2][4],
                                         int tid, int tm, int tn) {
    #pragma unroll
    for (int i = 0; i < 8; i++)
        #pragma unroll
        for (int j = 0; j < 2; j++)
            #pragma unroll
            for (int c = 0; c < 4; c++) acc[i][j][c] = 0.f;

    float4 pf[8];
    #pragma unroll
    for (int p = 0; p < 8; p++) {
        int idx = tid + p * 256;            // < 2048
        int kq = idx & 3, n = idx >> 2;     // n < 512
        pf[p] = *(const float4*)(Wg + (size_t)n * HH + kq * 4);
    }
    #pragma unroll 1
    for (int kt = 0; kt < 32; kt++) {       // 32 tiles of K=16
        __syncthreads();                    // previous consumers done with ws
        #pragma unroll
        for (int p = 0; p < 8; p++) {
            int idx = tid + p * 256;
            int kq = idx & 3, n = idx >> 2;
            ws[(kq*4+0)*LDH + n] = pf[p].x;
            ws[(kq*4+1)*LDH + n] = pf[p].y;
            ws[(kq*4+2)*LDH + n] = pf[p].z;
            ws[(kq*4+3)*LDH + n] = pf[p].w;
        }
        __syncthreads();
        if (kt < 31) {
            #pragma unroll
            for (int p = 0; p < 8; p++) {
                int idx = tid + p * 256;
                int kq = idx & 3, n = idx >> 2;
                pf[p] = *(const float4*)(Wg + (size_t)n * HH + (kt + 1) * 16 + kq * 4);
            }
        }
        #pragma unroll
        for (int k4 = 0; k4 < 4; k4++) {
            float4 a4[8];
            #pragma unroll
            for (int i = 0; i < 8; i++)
                a4[i] = *(const float4*)(sb + (tm + 4*i) * LDH + kt * 16 + k4 * 4);
            #pragma unroll
            for (int kk = 0; kk < 4; kk++) {
                const float* wrow = ws + (k4*4 + kk) * LDH + tn * 4;
                float4 b0 = *(const float4*)(wrow);
                float4 b1 = *(const float4*)(wrow + 256);
                #pragma unroll
                for (int i = 0; i < 8; i++) {
                    float av = GETC(a4[i], kk);
                    acc[i][0][0] += av * b0.x; acc[i][0][1] += av * b0.y;
                    acc[i][0][2] += av * b0.z; acc[i][0][3] += av * b0.w;
                    acc[i][1][0] += av * b1.x; acc[i][1][1] += av * b1.y;
                    acc[i][1][2] += av * b1.z; acc[i][1][3] += av * b1.w;
                }
            }
        }
    }
}

__global__ __launch_bounds__(256)
void rec_kernel(const float* __restrict__ w_t,  const float* __restrict__ w_rh,
                const float* __restrict__ w_zh, const float* __restrict__ w_hh,
                float* __restrict__ out) {
    extern __shared__ float smem[];
    float* bufA = smem;                 // h_t / rh / h_next
    float* bufB = smem + 32 * LDH;      // h_o
    float* ws   = smem + 64 * LDH;      // weight tile [16][516]

    const int rb0 = blockIdx.x * 32;    // batch rows owned by this block
    const int tid = threadIdx.x;
    const int tn = tid & 63, tm = tid >> 6;   // cols tn*4 + 256*j ; rows tm + 4*i

    for (int idx = tid; idx < 32 * LDH; idx += 256) bufA[idx] = 0.f;
    __syncthreads();

    float acc[8][2][4], zreg[8][2][4];

    for (int t = 0; t < TT; t++) {
        // ---- stage 1: h_o = sigmoid(pre_o + h @ w_t^T) -> bufB ----
        mm32x512(bufA, w_t, ws, acc, tid, tm, tn);
        #pragma unroll
        for (int i = 0; i < 8; i++) {
            int m = tm + 4*i;
            size_t prow = ((size_t)(rb0 + m) * TT + t) * HH;
            #pragma unroll
            for (int j = 0; j < 2; j++) {
                int n = tn * 4 + j * 256;
                float4 po = *(const float4*)&g_po[prow + n];
                float4 hv;
                hv.x = sigmoidf_(acc[i][j][0] + po.x);
                hv.y = sigmoidf_(acc[i][j][1] + po.y);
                hv.z = sigmoidf_(acc[i][j][2] + po.z);
                hv.w = sigmoidf_(acc[i][j][3] + po.w);
                *(float4*)&bufB[m * LDH + n] = hv;
            }
        }
        // (sync at top of next mm32x512 protects bufB)

        // ---- stage 2a: r = sigmoid(pre_r + h_o @ w_rh^T); bufA = r * h_o ----
        mm32x512(bufB, w_rh, ws, acc, tid, tm, tn);
        #pragma unroll
        for (int i = 0; i < 8; i++) {
            int m = tm + 4*i;
            size_t prow = ((size_t)(rb0 + m) * TT + t) * HH;
            #pragma unroll
            for (int j = 0; j < 2; j++) {
                int n = tn * 4 + j * 256;
                float4 pr = *(const float4*)&g_pr[prow + n];
                float4 ho = *(const float4*)&bufB[m * LDH + n];
                float4 rv;
                rv.x = sigmoidf_(acc[i][j][0] + pr.x) * ho.x;
                rv.y = sigmoidf_(acc[i][j][1] + pr.y) * ho.y;
                rv.z = sigmoidf_(acc[i][j][2] + pr.z) * ho.z;
                rv.w = sigmoidf_(acc[i][j][3] + pr.w) * ho.w;
                *(float4*)&bufA[m * LDH + n] = rv;
            }
        }

        // ---- stage 2b: z = sigmoid(pre_z + h_o @ w_zh^T), kept in regs ----
        mm32x512(bufB, w_zh, ws, zreg, tid, tm, tn);
        #pragma unroll
        for (int i = 0; i < 8; i++) {
            int m = tm + 4*i;
            size_t prow = ((size_t)(rb0 + m) * TT + t) * HH;
            #pragma unroll
            for (int j = 0; j < 2; j++) {
                int n = tn * 4 + j * 256;
                float4 pz = *(const float4*)&g_pz[prow + n];
                zreg[i][j][0] = sigmoidf_(zreg[i][j][0] + pz.x);
                zreg[i][j][1] = sigmoidf_(zreg[i][j][1] + pz.y);
                zreg[i][j][2] = sigmoidf_(zreg[i][j][2] + pz.z);
                zreg[i][j][3] = sigmoidf_(zreg[i][j][3] + pz.w);
            }
        }

        // ---- stage 3: h~ = tanh(pre_h + (r*h_o) @ w_hh^T);
        //               h = (1-z)*h_o + z*h~ -> bufA, out ----
        mm32x512(bufA, w_hh, ws, acc, tid, tm, tn);
        __syncthreads();    // all readers of bufA (rh) done before overwrite
        #pragma unroll
        for (int i = 0; i < 8; i++) {
            int m = tm + 4*i;
            size_t prow = ((size_t)(rb0 + m) * TT + t) * HH;
            #pragma unroll
            for (int j = 0; j < 2; j++) {
                int n = tn * 4 + j * 256;
                float4 ph = *(const float4*)&g_ph[prow + n];
                float4 ho = *(const float4*)&bufB[m * LDH + n];
                float4 hn;
                float z0 = zreg[i][j][0], z1 = zreg[i][j][1];
                float z2 = zreg[i][j][2], z3 = zreg[i][j][3];
                hn.x = (1.f - z0) * ho.x + z0 * tanhf(acc[i][j][0] + ph.x);
                hn.y = (1.f - z1) * ho.y + z1 * tanhf(acc[i][j][1] + ph.y);
                hn.z = (1.f - z2) * ho.z + z2 * tanhf(acc[i][j][2] + ph.z);
                hn.w = (1.f - z3) * ho.w + z3 * tanhf(acc[i][j][3] + ph.w);
                *(float4*)&bufA[m * LDH + n] = hn;
                *(float4*)&out[prow + n] = hn;
            }
        }
        __syncthreads();    // bufA complete before next step's stage 1
    }
}

// ============================================================================
// Launch
// ============================================================================
extern "C" void kernel_launch(void* const* d_in, const int* in_sizes, int n_in,
                              void* d_out, int out_size) {
    const float* x_input   = (const float*)d_in[0];
    const float* x_weather = (const float*)d_in[1];
    const float* w_rx = (const float*)d_in[2];
    const float* w_rh = (const float*)d_in[3];
    const float* w_re = (const float*)d_in[4];
    const float* b_r  = (const float*)d_in[5];
    const float* w_zx = (const float*)d_in[6];
    const float* w_zh = (const float*)d_in[7];
    const float* w_ze = (const float*)d_in[8];
    const float* b_z  = (const float*)d_in[9];
    const float* w_hx = (const float*)d_in[10];
    const float* w_hh = (const float*)d_in[11];
    const float* b_h  = (const float*)d_in[12];
    const float* w_d  = (const float*)d_in[13];
    const float* w_w  = (const float*)d_in[14];
    const float* w_m  = (const float*)d_in[15];
    const float* w_t  = (const float*)d_in[16];
    const float* w_e  = (const float*)d_in[17];
    const float* b_e  = (const float*)d_in[18];
    float* out = (float*)d_out;

    cudaFuncSetAttribute(rec_kernel, cudaFuncAttributeMaxDynamicSharedMemorySize,
                         REC_SMEM);

    e_kernel<<<dim3(BT/64, HH/128, 1), 256>>>(x_weather, w_e, b_e);
    pre_kernel<<<dim3(BT/128, HH/128, 4), 256>>>(x_input,
                                                 w_rx, w_re, b_r,
                                                 w_zx, w_ze, b_z,
                                                 w_hx, b_h,
                                                 w_d, w_w, w_m);
    rec_kernel<<<BB/32, 256, REC_SMEM>>>(w_t, w_rh, w_zh, w_hh, out);
}

// round 6
// speedup vs baseline: 1.5297x; 1.5226x over previous
#include <cuda_runtime.h>
#include <cuda_bf16.h>
#include <cstdint>
#include <cstddef>

#define BB 4096
#define TT 24
#define II 128
#define HH 512
#define WW 32
#define BT (BB*TT)

typedef __nv_bfloat16 bf16;

// packed bf16 weight offsets (elements)
#define OWT  0
#define OWRH (512*512)
#define OWZH (2*512*512)
#define OWHH (3*512*512)
#define OWRE (4*512*512)
#define OWZE (5*512*512)
#define OWRX (6*512*512)
#define OWZX (OWRX+512*128)
#define OWHX (OWRX+2*512*128)
#define OWD  (OWRX+3*512*128)
#define OWW  (OWRX+4*512*128)
#define OWM  (OWRX+5*512*128)
#define WTOT (OWRX+6*512*128)

// NOTE: __align__(256) is load-bearing — cp.async.16 needs 16B-aligned global
// sources and float2 paths need 8B; default align of bf16/float arrays is 2/4.
__device__ __align__(256) float g_po[(size_t)BT*HH];
__device__ __align__(256) float g_pr[(size_t)BT*HH];
__device__ __align__(256) float g_pz[(size_t)BT*HH];
__device__ __align__(256) float g_ph[(size_t)BT*HH];
__device__ __align__(256) bf16  g_Ehi[(size_t)BT*HH];
__device__ __align__(256) bf16  g_Elo[(size_t)BT*HH];
__device__ __align__(256) bf16  g_Xhi[(size_t)BT*II];
__device__ __align__(256) bf16  g_Xlo[(size_t)BT*II];
__device__ __align__(256) bf16  g_Whi[WTOT];
__device__ __align__(256) bf16  g_Wlo[WTOT];

__device__ __forceinline__ float sigmoidf_(float x){ return 1.0f/(1.0f+__expf(-x)); }
__device__ __forceinline__ uint32_t smemu(const void* p){ return (uint32_t)__cvta_generic_to_shared(p); }
__device__ __forceinline__ void bfsplit(float v, bf16& h, bf16& l){
    h = __float2bfloat16_rn(v);
    l = __float2bfloat16_rn(v - __bfloat162float(h));
}
__device__ __forceinline__ void ldsm4(uint32_t* r, uint32_t a){
    asm volatile("ldmatrix.sync.aligned.m8n8.x4.shared.b16 {%0,%1,%2,%3},[%4];"
        : "=r"(r[0]),"=r"(r[1]),"=r"(r[2]),"=r"(r[3]) : "r"(a));
}
__device__ __forceinline__ void mma16816(float* c, const uint32_t* a, uint32_t b0, uint32_t b1){
    asm volatile("mma.sync.aligned.m16n8k16.row.col.f32.bf16.bf16.f32 "
        "{%0,%1,%2,%3},{%4,%5,%6,%7},{%8,%9},{%0,%1,%2,%3};"
        : "+f"(c[0]),"+f"(c[1]),"+f"(c[2]),"+f"(c[3])
        : "r"(a[0]),"r"(a[1]),"r"(a[2]),"r"(a[3]),"r"(b0),"r"(b1));
}
__device__ __forceinline__ void cp16(uint32_t d, const void* s){
    asm volatile("cp.async.cg.shared.global [%0],[%1],16;" :: "r"(d),"l"(s) : "memory");
}
__device__ __forceinline__ void cp16z(uint32_t d, const void* s, int ok){
    asm volatile("cp.async.cg.shared.global [%0],[%1],16,%2;" :: "r"(d),"l"(s),"r"(ok?16:0) : "memory");
}
#define CPC()  asm volatile("cp.async.commit_group;" ::: "memory")
#define CPW1() asm volatile("cp.async.wait_group 1;" ::: "memory")
#define CPW0() asm volatile("cp.async.wait_group 0;" ::: "memory")

// ============================================================================
// weight / input bf16 hi-lo split
// ============================================================================
__global__ __launch_bounds__(256)
void conv_weights(const float* wt,const float* wrh,const float* wzh,const float* whh,
                  const float* wre,const float* wze,const float* wrx,const float* wzx,
                  const float* whx,const float* wd,const float* ww,const float* wm){
    int i = blockIdx.x*256 + threadIdx.x;
    if (i >= WTOT) return;
    const float* s; int off;
    if      (i < OWRH){ s=wt;  off=i; }
    else if (i < OWZH){ s=wrh; off=i-OWRH; }
    else if (i < OWHH){ s=wzh; off=i-OWZH; }
    else if (i < OWRE){ s=whh; off=i-OWHH; }
    else if (i < OWZE){ s=wre; off=i-OWRE; }
    else if (i < OWRX){ s=wze; off=i-OWZE; }
    else if (i < OWZX){ s=wrx; off=i-OWRX; }
    else if (i < OWHX){ s=wzx; off=i-OWZX; }
    else if (i < OWD ){ s=whx; off=i-OWHX; }
    else if (i < OWW ){ s=wd;  off=i-OWD;  }
    else if (i < OWM ){ s=ww;  off=i-OWW;  }
    else              { s=wm;  off=i-OWM;  }
    bfsplit(s[off], g_Whi[i], g_Wlo[i]);
}

__global__ __launch_bounds__(256)
void conv_x(const float* __restrict__ X){
    int i = blockIdx.x*256 + threadIdx.x;
    bfsplit(X[i], g_Xhi[i], g_Xlo[i]);
}

// ============================================================================
// E = sigmoid(XW @ w_e^T + b_e) -> bf16 hi/lo  (K=32, scalar fp32)
// ============================================================================
__global__ __launch_bounds__(256)
void e_kernel(const float* __restrict__ xw, const float* __restrict__ w_e,
              const float* __restrict__ b_e){
    __shared__ float As[32][68];
    __shared__ float Ws[32][132];
    const int r0 = blockIdx.x*64, c0 = blockIdx.y*128, tid = threadIdx.x;
    #pragma unroll
    for (int p=0;p<2;p++){
        int idx=tid+p*256; int m=idx>>3, kq=idx&7;
        float4 v = *(const float4*)(xw + (size_t)(r0+m)*WW + kq*4);
        As[kq*4+0][m]=v.x; As[kq*4+1][m]=v.y; As[kq*4+2][m]=v.z; As[kq*4+3][m]=v.w;
    }
    #pragma unroll
    for (int p=0;p<4;p++){
        int idx=tid+p*256; int n=idx>>3, kq=idx&7;
        float4 v = *(const float4*)(w_e + (size_t)(c0+n)*WW + kq*4);
        Ws[kq*4+0][n]=v.x; Ws[kq*4+1][n]=v.y; Ws[kq*4+2][n]=v.z; Ws[kq*4+3][n]=v.w;
    }
    __syncthreads();
    const int tm=tid>>4, tn=tid&15;
    float acc[4][8];
    #pragma unroll
    for (int i=0;i<4;i++) for (int j=0;j<8;j++) acc[i][j]=0.f;
    #pragma unroll 4
    for (int kk=0;kk<32;kk++){
        float a[4], b[8];
        #pragma unroll
        for (int i=0;i<4;i++) a[i]=As[kk][tm+16*i];
        #pragma unroll
        for (int j=0;j<8;j++) b[j]=Ws[kk][tn+16*j];
        #pragma unroll
        for (int i=0;i<4;i++)
            #pragma unroll
            for (int j=0;j<8;j++) acc[i][j]+=a[i]*b[j];
    }
    #pragma unroll
    for (int i=0;i<4;i++){
        int m=r0+tm+16*i;
        #pragma unroll
        for (int j=0;j<8;j++){
            int n=c0+tn+16*j;
            float v = sigmoidf_(acc[i][j] + b_e[n]);
            bfsplit(v, g_Ehi[(size_t)m*HH+n], g_Elo[(size_t)m*HH+n]);
        }
    }
}

// ============================================================================
// pre_mma: 128x128 block tiles, mma.sync bf16 3-pass, cp.async double-buffer.
// z: 0=pre_h  1=pre_r  2=pre_z  3=pre_o
// ============================================================================
#define PSTA 40            // smem row stride (bf16 elems), 80 B
#define PPL  (128*PSTA)    // plane size
#define PRE_SMEM (8*PPL*2) // 81920 B

__global__ __launch_bounds__(256,1)
void pre_mma(const float* __restrict__ b_r, const float* __restrict__ b_z,
             const float* __restrict__ b_h){
    extern __shared__ bf16 ps[];
    const int tid=threadIdx.x, wid=tid>>5, lane=tid&31;
    const int r0=blockIdx.x*128, c0=blockIdx.y*128, zc=blockIdx.z;

    const bf16 *Ah[3],*Al[3]; int Wo[3],Ks[3],Sh[3],nseg;
    const float* bias=nullptr; float* dst;
    if (zc==0){ nseg=1; Ah[0]=g_Xhi;Al[0]=g_Xlo;Wo[0]=OWHX;Ks[0]=II;Sh[0]=0; bias=b_h; dst=g_ph; }
    else if (zc==1){ nseg=2;
        Ah[0]=g_Xhi;Al[0]=g_Xlo;Wo[0]=OWRX;Ks[0]=II;Sh[0]=0;
        Ah[1]=g_Ehi;Al[1]=g_Elo;Wo[1]=OWRE;Ks[1]=HH;Sh[1]=0; bias=b_r; dst=g_pr; }
    else if (zc==2){ nseg=2;
        Ah[0]=g_Xhi;Al[0]=g_Xlo;Wo[0]=OWZX;Ks[0]=II;Sh[0]=0;
        Ah[1]=g_Ehi;Al[1]=g_Elo;Wo[1]=OWZE;Ks[1]=HH;Sh[1]=0; bias=b_z; dst=g_pz; }
    else { nseg=3;
        Ah[0]=g_Xhi;Al[0]=g_Xlo;Wo[0]=OWD;Ks[0]=II;Sh[0]=24;
        Ah[1]=g_Xhi;Al[1]=g_Xlo;Wo[1]=OWW;Ks[1]=II;Sh[1]=168;
        Ah[2]=g_Xhi;Al[2]=g_Xlo;Wo[2]=OWM;Ks[2]=II;Sh[2]=720; dst=g_po; }

    const int wm=wid>>2, wn=wid&3;
    float acc[4][4][4];
    #pragma unroll
    for (int i=0;i<4;i++) for (int j=0;j<4;j++) for (int c=0;c<4;c++) acc[i][j][c]=0.f;

    for (int s=0;s<nseg;s++){
        const bf16 *A0=Ah[s], *A1=Al[s];
        const bf16 *W0=g_Whi+Wo[s], *W1=g_Wlo+Wo[s];
        const int K=Ks[s], sh=Sh[s], nkt=K/32;

        #define PRE_LD(kt,buf) { \
            _Pragma("unroll") \
            for (int q=0;q<2;q++){ \
                int idx=tid*2+q; int row=idx>>2, c=(idx&3)*8; \
                int gr=r0+row-sh; int gok = gr>=0; int gc = gok?gr:0; \
                size_t ao=(size_t)gc*K + (kt)*32 + c; \
                cp16z(smemu(&ps[((buf)*2+0)*PPL + row*PSTA + c]), A0+ao, gok); \
                cp16z(smemu(&ps[((buf)*2+1)*PPL + row*PSTA + c]), A1+ao, gok); \
                size_t bo=(size_t)(c0+row)*K + (kt)*32 + c; \
                cp16(smemu(&ps[(4+(buf)*2+0)*PPL + row*PSTA + c]), W0+bo); \
                cp16(smemu(&ps[(4+(buf)*2+1)*PPL + row*PSTA + c]), W1+bo); \
            } \
            CPC(); }

        PRE_LD(0,0);
        for (int kt=0;kt<nkt;kt++){
            int buf=kt&1;
            if (kt+1<nkt) { PRE_LD(kt+1,buf^1); CPW1(); } else { CPW0(); }
            __syncthreads();
            #pragma unroll
            for (int ks=0;ks<2;ks++){
                int k0=ks*16;
                uint32_t ah[4][4], al[4][4];
                #pragma unroll
                for (int i=0;i<4;i++){
                    int rr = wm*64 + i*16 + (lane&7) + ((lane>>3)&1)*8;
                    int cc = k0 + (lane>>4)*8;
                    ldsm4(ah[i], smemu(&ps[(buf*2+0)*PPL + rr*PSTA + cc]));
                    ldsm4(al[i], smemu(&ps[(buf*2+1)*PPL + rr*PSTA + cc]));
                }
                uint32_t bh[2][4], bl[2][4];
                #pragma unroll
                for (int p=0;p<2;p++){
                    int nr = wn*32 + p*16 + ((lane>>4)&1)*8 + (lane&7);
                    int cc = k0 + ((lane>>3)&1)*8;
                    ldsm4(bh[p], smemu(&ps[(4+buf*2+0)*PPL + nr*PSTA + cc]));
                    ldsm4(bl[p], smemu(&ps[(4+buf*2+1)*PPL + nr*PSTA + cc]));
                }
                #pragma unroll
                for (int i=0;i<4;i++)
                    #pragma unroll
                    for (int j=0;j<4;j++){
                        uint32_t B0=bh[j>>1][(j&1)*2], B1=bh[j>>1][(j&1)*2+1];
                        uint32_t L0=bl[j>>1][(j&1)*2], L1=bl[j>>1][(j&1)*2+1];
                        mma16816(acc[i][j], ah[i], B0, B1);
                        mma16816(acc[i][j], ah[i], L0, L1);
                        mma16816(acc[i][j], al[i], B0, B1);
                    }
            }
            __syncthreads();
        }
    }

    const int mr = r0 + wm*64 + (lane>>2);
    const int nc = c0 + wn*32 + (lane&3)*2;
    #pragma unroll
    for (int i=0;i<4;i++){
        #pragma unroll
        for (int j=0;j<4;j++){
            int n = nc + j*8;
            float b0v=0.f, b1v=0.f;
            if (bias){ b0v=bias[n]; b1v=bias[n+1]; }
            int m0 = mr + i*16;
            float2 v0 = make_float2(acc[i][j][0]+b0v, acc[i][j][1]+b1v);
            float2 v1 = make_float2(acc[i][j][2]+b0v, acc[i][j][3]+b1v);
            *(float2*)&dst[(size_t)m0*HH + n] = v0;
            *(float2*)&dst[(size_t)(m0+8)*HH + n] = v1;
        }
    }
}

// ============================================================================
// rec_mma: persistent 128 blocks x 32 batch rows; h/h_o in smem bf16 hi/lo;
// weights streamed k16-tiled, double-buffered; mma.sync 3-pass.
// ============================================================================
#define RSTA 520                 // hA/hO row stride (bf16)
#define HPL  (32*RSTA)
#define WSTA 24                  // W tile row stride (bf16), 48 B
#define WPL  (512*WSTA)
#define REC_SMEM ((4*HPL + 4*WPL)*2)   // 231424 B

__device__ __forceinline__ void gemm_rec(const bf16* Asm, int woff, bf16* wt,
                                         float (&acc)[2][8][4],
                                         int tid, int wid, int lane){
    const bf16 *W0=g_Whi+woff, *W1=g_Wlo+woff;
    #pragma unroll
    for (int i=0;i<2;i++) for (int j=0;j<8;j++) for (int c=0;c<4;c++) acc[i][j][c]=0.f;

    #define REC_LD(kt,buf) { \
        _Pragma("unroll") \
        for (int q=0;q<4;q++){ \
            int idx=tid*4+q; int n=idx>>1, c=(idx&1)*8; \
            size_t so=(size_t)n*HH + (kt)*16 + c; \
            cp16(smemu(&wt[((buf)*2+0)*WPL + n*WSTA + c]), W0+so); \
            cp16(smemu(&wt[((buf)*2+1)*WPL + n*WSTA + c]), W1+so); \
        } \
        CPC(); }

    REC_LD(0,0);
    for (int kt=0;kt<32;kt++){
        int buf=kt&1;
        if (kt<31) { REC_LD(kt+1,buf^1); CPW1(); } else { CPW0(); }
        __syncthreads();
        uint32_t ah[2][4], al[2][4];
        #pragma unroll
        for (int i=0;i<2;i++){
            int rr = i*16 + (lane&7) + ((lane>>3)&1)*8;
            int cc = kt*16 + (lane>>4)*8;
            ldsm4(ah[i], smemu(Asm + 0*HPL + rr*RSTA + cc));
            ldsm4(al[i], smemu(Asm + 1*HPL + rr*RSTA + cc));
        }
        uint32_t bh[4][4], bl[4][4];
        #pragma unroll
        for (int p=0;p<4;p++){
            int nr = wid*64 + p*16 + ((lane>>4)&1)*8 + (lane&7);
            int cc = ((lane>>3)&1)*8;
            ldsm4(bh[p], smemu(&wt[(buf*2+0)*WPL + nr*WSTA + cc]));
            ldsm4(bl[p], smemu(&wt[(buf*2+1)*WPL + nr*WSTA + cc]));
        }
        #pragma unroll
        for (int i=0;i<2;i++)
            #pragma unroll
            for (int j=0;j<8;j++){
                uint32_t B0=bh[j>>1][(j&1)*2], B1=bh[j>>1][(j&1)*2+1];
                uint32_t L0=bl[j>>1][(j&1)*2], L1=bl[j>>1][(j&1)*2+1];
                mma16816(acc[i][j], ah[i], B0, B1);
                mma16816(acc[i][j], ah[i], L0, L1);
                mma16816(acc[i][j], al[i], B0, B1);
            }
        __syncthreads();
    }
}

__global__ __launch_bounds__(256,1)
void rec_mma(float* __restrict__ out){
    extern __shared__ bf16 rs[];
    bf16* hA = rs;
    bf16* hO = rs + 2*HPL;
    bf16* wt = rs + 4*HPL;

    const int tid=threadIdx.x, wid=tid>>5, lane=tid&31;
    const int rb0 = blockIdx.x*32;

    for (int i=tid; i<2*HPL; i+=256) hA[i] = __float2bfloat16(0.f);
    __syncthreads();

    float acc[2][8][4], zr[2][8][4];
    const int mb = lane>>2;
    const int nb = wid*64 + (lane&3)*2;

    for (int t=0;t<TT;t++){
        // stage 1: h_o = sigmoid(po + h @ w_t^T)
        gemm_rec(hA, OWT, wt, acc, tid, wid, lane);
        #pragma unroll
        for (int i=0;i<2;i++) for (int h2=0;h2<2;h2++){
            int m = i*16 + mb + h2*8;
            size_t pro = ((size_t)(rb0+m)*TT + t)*HH;
            #pragma unroll
            for (int j=0;j<8;j++){
                int n = nb + j*8;
                float2 p = *(const float2*)&g_po[pro + n];
                bf16 x0h,x0l,x1h,x1l;
                bfsplit(sigmoidf_(acc[i][j][h2*2+0]+p.x), x0h, x0l);
                bfsplit(sigmoidf_(acc[i][j][h2*2+1]+p.y), x1h, x1l);
                *(__nv_bfloat162*)&hO[0*HPL + m*RSTA + n] = __nv_bfloat162(x0h,x1h);
                *(__nv_bfloat162*)&hO[1*HPL + m*RSTA + n] = __nv_bfloat162(x0l,x1l);
            }
        }
        // stage 2a: r = sigmoid(pr + h_o@w_rh^T); hA = r*h_o
        gemm_rec(hO, OWRH, wt, acc, tid, wid, lane);
        #pragma unroll
        for (int i=0;i<2;i++) for (int h2=0;h2<2;h2++){
            int m = i*16 + mb + h2*8;
            size_t pro = ((size_t)(rb0+m)*TT + t)*HH;
            #pragma unroll
            for (int j=0;j<8;j++){
                int n = nb + j*8;
                float2 p = *(const float2*)&g_pr[pro + n];
                __nv_bfloat162 oh = *(__nv_bfloat162*)&hO[0*HPL + m*RSTA + n];
                __nv_bfloat162 ol = *(__nv_bfloat162*)&hO[1*HPL + m*RSTA + n];
                float ho0 = __bfloat162float(oh.x)+__bfloat162float(ol.x);
                float ho1 = __bfloat162float(oh.y)+__bfloat162float(ol.y);
                bf16 x0h,x0l,x1h,x1l;
                bfsplit(sigmoidf_(acc[i][j][h2*2+0]+p.x)*ho0, x0h, x0l);
                bfsplit(sigmoidf_(acc[i][j][h2*2+1]+p.y)*ho1, x1h, x1l);
                *(__nv_bfloat162*)&hA[0*HPL + m*RSTA + n] = __nv_bfloat162(x0h,x1h);
                *(__nv_bfloat162*)&hA[1*HPL + m*RSTA + n] = __nv_bfloat162(x0l,x1l);
            }
        }
        // stage 2b: z = sigmoid(pz + h_o@w_zh^T), in regs
        gemm_rec(hO, OWZH, wt, zr, tid, wid, lane);
        #pragma unroll
        for (int i=0;i<2;i++) for (int h2=0;h2<2;h2++){
            int m = i*16 + mb + h2*8;
            size_t pro = ((size_t)(rb0+m)*TT + t)*HH;
            #pragma unroll
            for (int j=0;j<8;j++){
                int n = nb + j*8;
                float2 p = *(const float2*)&g_pz[pro + n];
                zr[i][j][h2*2+0] = sigmoidf_(zr[i][j][h2*2+0]+p.x);
                zr[i][j][h2*2+1] = sigmoidf_(zr[i][j][h2*2+1]+p.y);
            }
        }
        // stage 3: h~ = tanh(ph + (r*h_o)@w_hh^T); h = (1-z)h_o + z h~
        gemm_rec(hA, OWHH, wt, acc, tid, wid, lane);
        #pragma unroll
        for (int i=0;i<2;i++) for (int h2=0;h2<2;h2++){
            int m = i*16 + mb + h2*8;
            size_t pro = ((size_t)(rb0+m)*TT + t)*HH;
            #pragma unroll
            for (int j=0;j<8;j++){
                int n = nb + j*8;
                float2 p = *(const float2*)&g_ph[pro + n];
                __nv_bfloat162 oh = *(__nv_bfloat162*)&hO[0*HPL + m*RSTA + n];
                __nv_bfloat162 ol = *(__nv_bfloat162*)&hO[1*HPL + m*RSTA + n];
                float ho0 = __bfloat162float(oh.x)+__bfloat162float(ol.x);
                float ho1 = __bfloat162float(oh.y)+__bfloat162float(ol.y);
                float z0 = zr[i][j][h2*2+0], z1 = zr[i][j][h2*2+1];
                float hn0 = (1.f-z0)*ho0 + z0*tanhf(acc[i][j][h2*2+0]+p.x);
                float hn1 = (1.f-z1)*ho1 + z1*tanhf(acc[i][j][h2*2+1]+p.y);
                bf16 x0h,x0l,x1h,x1l;
                bfsplit(hn0, x0h, x0l);
                bfsplit(hn1, x1h, x1l);
                *(__nv_bfloat162*)&hA[0*HPL + m*RSTA + n] = __nv_bfloat162(x0h,x1h);
                *(__nv_bfloat162*)&hA[1*HPL + m*RSTA + n] = __nv_bfloat162(x0l,x1l);
                *(float2*)&out[pro + n] = make_float2(hn0, hn1);
            }
        }
        __syncthreads();
    }
}

// ============================================================================
// launch
// ============================================================================
extern "C" void kernel_launch(void* const* d_in, const int* in_sizes, int n_in,
                              void* d_out, int out_size){
    const float* x_input   = (const float*)d_in[0];
    const float* x_weather = (const float*)d_in[1];
    const float* w_rx=(const float*)d_in[2],  *w_rh=(const float*)d_in[3];
    const float* w_re=(const float*)d_in[4],  *b_r =(const float*)d_in[5];
    const float* w_zx=(const float*)d_in[6],  *w_zh=(const float*)d_in[7];
    const float* w_ze=(const float*)d_in[8],  *b_z =(const float*)d_in[9];
    const float* w_hx=(const float*)d_in[10], *w_hh=(const float*)d_in[11];
    const float* b_h =(const float*)d_in[12];
    const float* w_d =(const float*)d_in[13], *w_w =(const float*)d_in[14];
    const float* w_m =(const float*)d_in[15], *w_t =(const float*)d_in[16];
    const float* w_e =(const float*)d_in[17], *b_e =(const float*)d_in[18];
    float* out = (float*)d_out;

    cudaFuncSetAttribute(pre_mma, cudaFuncAttributeMaxDynamicSharedMemorySize, PRE_SMEM);
    cudaFuncSetAttribute(rec_mma, cudaFuncAttributeMaxDynamicSharedMemorySize, REC_SMEM);

    conv_weights<<<(WTOT+255)/256, 256>>>(w_t,w_rh,w_zh,w_hh,w_re,w_ze,
                                          w_rx,w_zx,w_hx,w_d,w_w,w_m);
    conv_x<<<(BT*II)/256, 256>>>(x_input);
    e_kernel<<<dim3(BT/64, HH/128, 1), 256>>>(x_weather, w_e, b_e);
    pre_mma<<<dim3(BT/128, HH/128, 4), 256, PRE_SMEM>>>(b_r, b_z, b_h);
    rec_mma<<<BB/32, 256, REC_SMEM>>>(out);
}

// round 9
// speedup vs baseline: 1.7928x; 1.1720x over previous
#include <cuda_runtime.h>
#include <cuda_bf16.h>
#include <cstdint>
#include <cstddef>

#define BB 4096
#define TT 24
#define II 128
#define HH 512
#define WW 32
#define BT (BB*TT)

typedef __nv_bfloat16 bf16;

// packed bf16 weight offsets (elements)
#define OWT  0
#define OWRH (512*512)
#define OWZH (2*512*512)
#define OWHH (3*512*512)
#define OWRE (4*512*512)
#define OWZE (5*512*512)
#define OWRX (6*512*512)
#define OWZX (OWRX+512*128)
#define OWHX (OWRX+2*512*128)
#define OWD  (OWRX+3*512*128)
#define OWW  (OWRX+4*512*128)
#define OWM  (OWRX+5*512*128)
#define WTOT (OWRX+6*512*128)

// __align__(256) is load-bearing: cp.async.16 needs 16B-aligned global srcs.
__device__ __align__(256) float g_po[(size_t)BT*HH];
__device__ __align__(256) float g_pr[(size_t)BT*HH];
__device__ __align__(256) float g_pz[(size_t)BT*HH];
__device__ __align__(256) float g_ph[(size_t)BT*HH];
__device__ __align__(256) bf16  g_Ehi[(size_t)BT*HH];
__device__ __align__(256) bf16  g_Elo[(size_t)BT*HH];
__device__ __align__(256) bf16  g_Xhi[(size_t)BT*II];
__device__ __align__(256) bf16  g_Xlo[(size_t)BT*II];
__device__ __align__(256) bf16  g_Whi[WTOT];
__device__ __align__(256) bf16  g_Wlo[WTOT];

__device__ __forceinline__ float sigmoidf_(float x){ return 1.0f/(1.0f+__expf(-x)); }
__device__ __forceinline__ float tanhfast_(float x){ return 2.0f/(1.0f+__expf(-2.0f*x)) - 1.0f; }
__device__ __forceinline__ uint32_t smemu(const void* p){ return (uint32_t)__cvta_generic_to_shared(p); }
__device__ __forceinline__ void bfsplit(float v, bf16& h, bf16& l){
    h = __float2bfloat16_rn(v);
    l = __float2bfloat16_rn(v - __bfloat162float(h));
}
__device__ __forceinline__ void ldsm4(uint32_t* r, uint32_t a){
    asm volatile("ldmatrix.sync.aligned.m8n8.x4.shared.b16 {%0,%1,%2,%3},[%4];"
        : "=r"(r[0]),"=r"(r[1]),"=r"(r[2]),"=r"(r[3]) : "r"(a));
}
__device__ __forceinline__ void mma16816(float* c, const uint32_t* a, uint32_t b0, uint32_t b1){
    asm volatile("mma.sync.aligned.m16n8k16.row.col.f32.bf16.bf16.f32 "
        "{%0,%1,%2,%3},{%4,%5,%6,%7},{%8,%9},{%0,%1,%2,%3};"
        : "+f"(c[0]),"+f"(c[1]),"+f"(c[2]),"+f"(c[3])
        : "r"(a[0]),"r"(a[1]),"r"(a[2]),"r"(a[3]),"r"(b0),"r"(b1));
}
__device__ __forceinline__ void cp16(uint32_t d, const void* s){
    asm volatile("cp.async.cg.shared.global [%0],[%1],16;" :: "r"(d),"l"(s) : "memory");
}
__device__ __forceinline__ void cp16z(uint32_t d, const void* s, int ok){
    asm volatile("cp.async.cg.shared.global [%0],[%1],16,%2;" :: "r"(d),"l"(s),"r"(ok?16:0) : "memory");
}
#define CPC()  asm volatile("cp.async.commit_group;" ::: "memory")
#define CPW1() asm volatile("cp.async.wait_group 1;" ::: "memory")
#define CPW0() asm volatile("cp.async.wait_group 0;" ::: "memory")

// ============================================================================
// weight / input bf16 hi-lo split
// ============================================================================
__global__ __launch_bounds__(256)
void conv_weights(const float* wt,const float* wrh,const float* wzh,const float* whh,
                  const float* wre,const float* wze,const float* wrx,const float* wzx,
                  const float* whx,const float* wd,const float* ww,const float* wm){
    int i = blockIdx.x*256 + threadIdx.x;
    if (i >= WTOT) return;
    const float* s; int off;
    if      (i < OWRH){ s=wt;  off=i; }
    else if (i < OWZH){ s=wrh; off=i-OWRH; }
    else if (i < OWHH){ s=wzh; off=i-OWZH; }
    else if (i < OWRE){ s=whh; off=i-OWHH; }
    else if (i < OWZE){ s=wre; off=i-OWRE; }
    else if (i < OWRX){ s=wze; off=i-OWZE; }
    else if (i < OWZX){ s=wrx; off=i-OWRX; }
    else if (i < OWHX){ s=wzx; off=i-OWZX; }
    else if (i < OWD ){ s=whx; off=i-OWHX; }
    else if (i < OWW ){ s=wd;  off=i-OWD;  }
    else if (i < OWM ){ s=ww;  off=i-OWW;  }
    else              { s=wm;  off=i-OWM;  }
    bfsplit(s[off], g_Whi[i], g_Wlo[i]);
}

__global__ __launch_bounds__(256)
void conv_x(const float* __restrict__ X){
    int i = blockIdx.x*256 + threadIdx.x;
    bfsplit(X[i], g_Xhi[i], g_Xlo[i]);
}

// ============================================================================
// E = sigmoid(XW @ w_e^T + b_e) -> bf16 hi/lo  (K=32, scalar fp32)
// ============================================================================
__global__ __launch_bounds__(256)
void e_kernel(const float* __restrict__ xw, const float* __restrict__ w_e,
              const float* __restrict__ b_e){
    __shared__ float As[32][68];
    __shared__ float Ws[32][132];
    const int r0 = blockIdx.x*64, c0 = blockIdx.y*128, tid = threadIdx.x;
    #pragma unroll
    for (int p=0;p<2;p++){
        int idx=tid+p*256; int m=idx>>3, kq=idx&7;
        float4 v = *(const float4*)(xw + (size_t)(r0+m)*WW + kq*4);
        As[kq*4+0][m]=v.x; As[kq*4+1][m]=v.y; As[kq*4+2][m]=v.z; As[kq*4+3][m]=v.w;
    }
    #pragma unroll
    for (int p=0;p<4;p++){
        int idx=tid+p*256; int n=idx>>3, kq=idx&7;
        float4 v = *(const float4*)(w_e + (size_t)(c0+n)*WW + kq*4);
        Ws[kq*4+0][n]=v.x; Ws[kq*4+1][n]=v.y; Ws[kq*4+2][n]=v.z; Ws[kq*4+3][n]=v.w;
    }
    __syncthreads();
    const int tm=tid>>4, tn=tid&15;
    float acc[4][8];
    #pragma unroll
    for (int i=0;i<4;i++) for (int j=0;j<8;j++) acc[i][j]=0.f;
    #pragma unroll 4
    for (int kk=0;kk<32;kk++){
        float a[4], b[8];
        #pragma unroll
        for (int i=0;i<4;i++) a[i]=As[kk][tm+16*i];
        #pragma unroll
        for (int j=0;j<8;j++) b[j]=Ws[kk][tn+16*j];
        #pragma unroll
        for (int i=0;i<4;i++)
            #pragma unroll
            for (int j=0;j<8;j++) acc[i][j]+=a[i]*b[j];
    }
    #pragma unroll
    for (int i=0;i<4;i++){
        int m=r0+tm+16*i;
        #pragma unroll
        for (int j=0;j<8;j++){
            int n=c0+tn+16*j;
            float v = sigmoidf_(acc[i][j] + b_e[n]);
            bfsplit(v, g_Ehi[(size_t)m*HH+n], g_Elo[(size_t)m*HH+n]);
        }
    }
}

// ============================================================================
// pre_mma: 128x128 block tiles, mma.sync bf16 3-pass, cp.async double-buffer.
// launch_bounds(256,2) caps regs at 128 -> 2 CTAs/SM (round-6: regs=144 forced
// occ=1 CTA, tensor stuck at 47%). Two syncs per k-tile (needed for 2-buffer).
// z: 0=pre_h  1=pre_r  2=pre_z  3=pre_o
// ============================================================================
#define PSTA 40
#define PPL  (128*PSTA)
#define PRE_SMEM (8*PPL*2)   // 81920 B -> 2 CTAs/SM fits

__global__ __launch_bounds__(256,2)
void pre_mma(const float* __restrict__ b_r, const float* __restrict__ b_z,
             const float* __restrict__ b_h){
    extern __shared__ bf16 ps[];
    const int tid=threadIdx.x, wid=tid>>5, lane=tid&31;
    const int r0=blockIdx.x*128, c0=blockIdx.y*128, zc=blockIdx.z;

    const bf16 *Ah[3],*Al[3]; int Wo[3],Ks[3],Sh[3],nseg;
    const float* bias=nullptr; float* dst;
    if (zc==0){ nseg=1; Ah[0]=g_Xhi;Al[0]=g_Xlo;Wo[0]=OWHX;Ks[0]=II;Sh[0]=0; bias=b_h; dst=g_ph; }
    else if (zc==1){ nseg=2;
        Ah[0]=g_Xhi;Al[0]=g_Xlo;Wo[0]=OWRX;Ks[0]=II;Sh[0]=0;
        Ah[1]=g_Ehi;Al[1]=g_Elo;Wo[1]=OWRE;Ks[1]=HH;Sh[1]=0; bias=b_r; dst=g_pr; }
    else if (zc==2){ nseg=2;
        Ah[0]=g_Xhi;Al[0]=g_Xlo;Wo[0]=OWZX;Ks[0]=II;Sh[0]=0;
        Ah[1]=g_Ehi;Al[1]=g_Elo;Wo[1]=OWZE;Ks[1]=HH;Sh[1]=0; bias=b_z; dst=g_pz; }
    else { nseg=3;
        Ah[0]=g_Xhi;Al[0]=g_Xlo;Wo[0]=OWD;Ks[0]=II;Sh[0]=24;
        Ah[1]=g_Xhi;Al[1]=g_Xlo;Wo[1]=OWW;Ks[1]=II;Sh[1]=168;
        Ah[2]=g_Xhi;Al[2]=g_Xlo;Wo[2]=OWM;Ks[2]=II;Sh[2]=720; dst=g_po; }

    const int wm=wid>>2, wn=wid&3;
    float acc[4][4][4];
    #pragma unroll
    for (int i=0;i<4;i++) for (int j=0;j<4;j++) for (int c=0;c<4;c++) acc[i][j][c]=0.f;

    for (int s=0;s<nseg;s++){
        const bf16 *A0=Ah[s], *A1=Al[s];
        const bf16 *W0=g_Whi+Wo[s], *W1=g_Wlo+Wo[s];
        const int K=Ks[s], sh=Sh[s], nkt=K/32;

        #define PRE_LD(kt,buf) { \
            _Pragma("unroll") \
            for (int q=0;q<2;q++){ \
                int idx=tid*2+q; int row=idx>>2, c=(idx&3)*8; \
                int gr=r0+row-sh; int gok = gr>=0; int gc = gok?gr:0; \
                size_t ao=(size_t)gc*K + (size_t)(kt)*32 + c; \
                cp16z(smemu(&ps[((buf)*2+0)*PPL + row*PSTA + c]), A0+ao, gok); \
                cp16z(smemu(&ps[((buf)*2+1)*PPL + row*PSTA + c]), A1+ao, gok); \
                size_t bo=(size_t)(c0+row)*K + (size_t)(kt)*32 + c; \
                cp16(smemu(&ps[(4+(buf)*2+0)*PPL + row*PSTA + c]), W0+bo); \
                cp16(smemu(&ps[(4+(buf)*2+1)*PPL + row*PSTA + c]), W1+bo); \
            } \
            CPC(); }

        PRE_LD(0,0);
        for (int kt=0;kt<nkt;kt++){
            int buf=kt&1;
            if (kt+1<nkt) { PRE_LD(kt+1,buf^1); CPW1(); } else { CPW0(); }
            __syncthreads();
            #pragma unroll
            for (int ks=0;ks<2;ks++){
                int k0=ks*16;
                uint32_t ah[4][4], al[4][4];
                #pragma unroll
                for (int i=0;i<4;i++){
                    int rr = wm*64 + i*16 + (lane&7) + ((lane>>3)&1)*8;
                    int cc = k0 + (lane>>4)*8;
                    ldsm4(ah[i], smemu(&ps[(buf*2+0)*PPL + rr*PSTA + cc]));
                    ldsm4(al[i], smemu(&ps[(buf*2+1)*PPL + rr*PSTA + cc]));
                }
                uint32_t bh[2][4], bl[2][4];
                #pragma unroll
                for (int p=0;p<2;p++){
                    int nr = wn*32 + p*16 + ((lane>>4)&1)*8 + (lane&7);
                    int cc = k0 + ((lane>>3)&1)*8;
                    ldsm4(bh[p], smemu(&ps[(4+buf*2+0)*PPL + nr*PSTA + cc]));
                    ldsm4(bl[p], smemu(&ps[(4+buf*2+1)*PPL + nr*PSTA + cc]));
                }
                #pragma unroll
                for (int i=0;i<4;i++)
                    #pragma unroll
                    for (int j=0;j<4;j++){
                        uint32_t B0=bh[j>>1][(j&1)*2], B1=bh[j>>1][(j&1)*2+1];
                        uint32_t L0=bl[j>>1][(j&1)*2], L1=bl[j>>1][(j&1)*2+1];
                        mma16816(acc[i][j], ah[i], B0, B1);
                        mma16816(acc[i][j], ah[i], L0, L1);
                        mma16816(acc[i][j], al[i], B0, B1);
                    }
            }
            __syncthreads();
        }
    }

    const int mr = r0 + wm*64 + (lane>>2);
    const int nc = c0 + wn*32 + (lane&3)*2;
    #pragma unroll
    for (int i=0;i<4;i++){
        #pragma unroll
        for (int j=0;j<4;j++){
            int n = nc + j*8;
            float b0v=0.f, b1v=0.f;
            if (bias){ b0v=bias[n]; b1v=bias[n+1]; }
            int m0 = mr + i*16;
            float2 v0 = make_float2(acc[i][j][0]+b0v, acc[i][j][1]+b1v);
            float2 v1 = make_float2(acc[i][j][2]+b0v, acc[i][j][3]+b1v);
            *(float2*)&dst[(size_t)m0*HH + n] = v0;
            *(float2*)&dst[(size_t)(m0+8)*HH + n] = v1;
        }
    }
}

// ============================================================================
// rec_mma: persistent 128 blocks x 32 batch rows.
// Compact weight tiles (32B rows + XOR-bit4 swizzle, no padding) -> smem for a
// 3-stage cp.async pipeline with ONE sync per k-tile.
// RACE-FIX vs round 8: REC_LD(kt+2) is issued AFTER the iteration's
// __syncthreads — buffer (kt+2)%3 == (kt-1)%3 was read at iter kt-1, and the
// sync proves all warps finished those reads before the overwrite.
// ============================================================================
#define RSTA 520
#define HPL  (32*RSTA)
#define WCH  16384                 // one weight chunk plane: 512 rows x 32B
#define REC_SMEM (4*HPL*2 + 6*WCH) // 133120 + 98304 = 231424 B

__device__ __forceinline__ void gemm_rec(const bf16* Asm, int woff, uint32_t wtb,
                                         float (&acc)[2][8][4],
                                         int tid, int wid, int lane){
    const bf16 *W0=g_Whi+woff, *W1=g_Wlo+woff;
    #pragma unroll
    for (int i=0;i<2;i++) for (int j=0;j<8;j++) for (int c=0;c<4;c++) acc[i][j][c]=0.f;

    // swizzled store: row n (32B) + chunk c (16B); bit4 ^= bit7
    #define REC_LD(kt,buf) { \
        _Pragma("unroll") \
        for (int q=0;q<4;q++){ \
            int idx=tid*4+q; int n=idx>>1, c=idx&1; \
            uint32_t by = (uint32_t)n*32u + (uint32_t)c*16u; \
            by ^= (by>>3)&0x10u; \
            size_t so=(size_t)n*HH + (size_t)(kt)*16 + c*8; \
            cp16(wtb + ((buf)*2+0)*WCH + by, W0+so); \
            cp16(wtb + ((buf)*2+1)*WCH + by, W1+so); \
        } \
        CPC(); }

    __syncthreads();   // prior gemm's wt readers + epilogue smem writes done
    REC_LD(0,0);
    REC_LD(1,1);
    #pragma unroll 1
    for (int kt=0;kt<32;kt++){
        int buf = kt % 3;
        if (kt<31) { CPW1(); } else { CPW0(); }   // group kt complete
        __syncthreads();                          // visible to all; iter kt-1 reads done

        uint32_t ah[2][4], al[2][4];
        #pragma unroll
        for (int i=0;i<2;i++){
            int rr = i*16 + (lane&7) + ((lane>>3)&1)*8;
            int cc = kt*16 + (lane>>4)*8;
            ldsm4(ah[i], smemu(Asm + 0*HPL + rr*RSTA + cc));
            ldsm4(al[i], smemu(Asm + 1*HPL + rr*RSTA + cc));
        }
        uint32_t bh[4][4], bl[4][4];
        #pragma unroll
        for (int p=0;p<4;p++){
            int nr = wid*64 + p*16 + ((lane>>4)&1)*8 + (lane&7);
            uint32_t by = (uint32_t)nr*32u + ((lane>>3)&1)*16u;
            by ^= (by>>3)&0x10u;
            ldsm4(bh[p], wtb + (buf*2+0)*WCH + by);
            ldsm4(bl[p], wtb + (buf*2+1)*WCH + by);
        }
        if (kt < 30) { REC_LD(kt+2, (kt+2)%3); }  // safe: after sync (see header)

        #pragma unroll
        for (int i=0;i<2;i++)
            #pragma unroll
            for (int j=0;j<8;j++){
                uint32_t B0=bh[j>>1][(j&1)*2], B1=bh[j>>1][(j&1)*2+1];
                uint32_t L0=bl[j>>1][(j&1)*2], L1=bl[j>>1][(j&1)*2+1];
                mma16816(acc[i][j], ah[i], B0, B1);
                mma16816(acc[i][j], ah[i], L0, L1);
                mma16816(acc[i][j], al[i], B0, B1);
            }
    }
    // no trailing sync: next gemm's entry sync protects wt/A reuse
}

__global__ __launch_bounds__(256,1)
void rec_mma(float* __restrict__ out){
    extern __shared__ bf16 rs[];
    bf16* hA = rs;
    bf16* hO = rs + 2*HPL;
    const uint32_t wtb = smemu(rs) + 4*HPL*2;   // byte offset of wt region

    const int tid=threadIdx.x, wid=tid>>5, lane=tid&31;
    const int rb0 = blockIdx.x*32;

    for (int i=tid; i<2*HPL; i+=256) hA[i] = __float2bfloat16(0.f);
    __syncthreads();

    float acc[2][8][4], zr[2][8][4];
    const int mb = lane>>2;
    const int nb = wid*64 + (lane&3)*2;

    for (int t=0;t<TT;t++){
        // stage 1: h_o = sigmoid(po + h @ w_t^T) -> hO
        gemm_rec(hA, OWT, wtb, acc, tid, wid, lane);
        #pragma unroll
        for (int i=0;i<2;i++) for (int h2=0;h2<2;h2++){
            int m = i*16 + mb + h2*8;
            size_t pro = ((size_t)(rb0+m)*TT + t)*HH;
            #pragma unroll
            for (int j=0;j<8;j++){
                int n = nb + j*8;
                float2 p = *(const float2*)&g_po[pro + n];
                bf16 x0h,x0l,x1h,x1l;
                bfsplit(sigmoidf_(acc[i][j][h2*2+0]+p.x), x0h, x0l);
                bfsplit(sigmoidf_(acc[i][j][h2*2+1]+p.y), x1h, x1l);
                *(__nv_bfloat162*)&hO[0*HPL + m*RSTA + n] = __nv_bfloat162(x0h,x1h);
                *(__nv_bfloat162*)&hO[1*HPL + m*RSTA + n] = __nv_bfloat162(x0l,x1l);
            }
        }
        // stage 2a: r = sigmoid(pr + h_o@w_rh^T); hA = r*h_o
        gemm_rec(hO, OWRH, wtb, acc, tid, wid, lane);
        #pragma unroll
        for (int i=0;i<2;i++) for (int h2=0;h2<2;h2++){
            int m = i*16 + mb + h2*8;
            size_t pro = ((size_t)(rb0+m)*TT + t)*HH;
            #pragma unroll
            for (int j=0;j<8;j++){
                int n = nb + j*8;
                float2 p = *(const float2*)&g_pr[pro + n];
                __nv_bfloat162 oh = *(__nv_bfloat162*)&hO[0*HPL + m*RSTA + n];
                __nv_bfloat162 ol = *(__nv_bfloat162*)&hO[1*HPL + m*RSTA + n];
                float ho0 = __bfloat162float(oh.x)+__bfloat162float(ol.x);
                float ho1 = __bfloat162float(oh.y)+__bfloat162float(ol.y);
                bf16 x0h,x0l,x1h,x1l;
                bfsplit(sigmoidf_(acc[i][j][h2*2+0]+p.x)*ho0, x0h, x0l);
                bfsplit(sigmoidf_(acc[i][j][h2*2+1]+p.y)*ho1, x1h, x1l);
                *(__nv_bfloat162*)&hA[0*HPL + m*RSTA + n] = __nv_bfloat162(x0h,x1h);
                *(__nv_bfloat162*)&hA[1*HPL + m*RSTA + n] = __nv_bfloat162(x0l,x1l);
            }
        }
        // stage 2b: z = sigmoid(pz + h_o@w_zh^T), in regs
        gemm_rec(hO, OWZH, wtb, zr, tid, wid, lane);
        #pragma unroll
        for (int i=0;i<2;i++) for (int h2=0;h2<2;h2++){
            int m = i*16 + mb + h2*8;
            size_t pro = ((size_t)(rb0+m)*TT + t)*HH;
            #pragma unroll
            for (int j=0;j<8;j++){
                int n = nb + j*8;
                float2 p = *(const float2*)&g_pz[pro + n];
                zr[i][j][h2*2+0] = sigmoidf_(zr[i][j][h2*2+0]+p.x);
                zr[i][j][h2*2+1] = sigmoidf_(zr[i][j][h2*2+1]+p.y);
            }
        }
        // stage 3: h~ = tanh(ph + (r*h_o)@w_hh^T); h = (1-z)h_o + z h~
        gemm_rec(hA, OWHH, wtb, acc, tid, wid, lane);
        __syncthreads();    // all warps' kt=31 reads of hA done before overwrite
        #pragma unroll
        for (int i=0;i<2;i++) for (int h2=0;h2<2;h2++){
            int m = i*16 + mb + h2*8;
            size_t pro = ((size_t)(rb0+m)*TT + t)*HH;
            #pragma unroll
            for (int j=0;j<8;j++){
                int n = nb + j*8;
                float2 p = *(const float2*)&g_ph[pro + n];
                __nv_bfloat162 oh = *(__nv_bfloat162*)&hO[0*HPL + m*RSTA + n];
                __nv_bfloat162 ol = *(__nv_bfloat162*)&hO[1*HPL + m*RSTA + n];
                float ho0 = __bfloat162float(oh.x)+__bfloat162float(ol.x);
                float ho1 = __bfloat162float(oh.y)+__bfloat162float(ol.y);
                float z0 = zr[i][j][h2*2+0], z1 = zr[i][j][h2*2+1];
                float hn0 = (1.f-z0)*ho0 + z0*tanhfast_(acc[i][j][h2*2+0]+p.x);
                float hn1 = (1.f-z1)*ho1 + z1*tanhfast_(acc[i][j][h2*2+1]+p.y);
                bf16 x0h,x0l,x1h,x1l;
                bfsplit(hn0, x0h, x0l);
                bfsplit(hn1, x1h, x1l);
                *(__nv_bfloat162*)&hA[0*HPL + m*RSTA + n] = __nv_bfloat162(x0h,x1h);
                *(__nv_bfloat162*)&hA[1*HPL + m*RSTA + n] = __nv_bfloat162(x0l,x1l);
                *(float2*)&out[pro + n] = make_float2(hn0, hn1);
            }
        }
        // next gemm's entry sync protects hA
    }
}

// ============================================================================
// launch
// ============================================================================
extern "C" void kernel_launch(void* const* d_in, const int* in_sizes, int n_in,
                              void* d_out, int out_size){
    const float* x_input   = (const float*)d_in[0];
    const float* x_weather = (const float*)d_in[1];
    const float* w_rx=(const float*)d_in[2],  *w_rh=(const float*)d_in[3];
    const float* w_re=(const float*)d_in[4],  *b_r =(const float*)d_in[5];
    const float* w_zx=(const float*)d_in[6],  *w_zh=(const float*)d_in[7];
    const float* w_ze=(const float*)d_in[8],  *b_z =(const float*)d_in[9];
    const float* w_hx=(const float*)d_in[10], *w_hh=(const float*)d_in[11];
    const float* b_h =(const float*)d_in[12];
    const float* w_d =(const float*)d_in[13], *w_w =(const float*)d_in[14];
    const float* w_m =(const float*)d_in[15], *w_t =(const float*)d_in[16];
    const float* w_e =(const float*)d_in[17], *b_e =(const float*)d_in[18];
    float* out = (float*)d_out;

    cudaFuncSetAttribute(pre_mma, cudaFuncAttributeMaxDynamicSharedMemorySize, PRE_SMEM);
    cudaFuncSetAttribute(rec_mma, cudaFuncAttributeMaxDynamicSharedMemorySize, REC_SMEM);

    conv_weights<<<(WTOT+255)/256, 256>>>(w_t,w_rh,w_zh,w_hh,w_re,w_ze,
                                          w_rx,w_zx,w_hx,w_d,w_w,w_m);
    conv_x<<<(BT*II)/256, 256>>>(x_input);
    e_kernel<<<dim3(BT/64, HH/128, 1), 256>>>(x_weather, w_e, b_e);
    pre_mma<<<dim3(BT/128, HH/128, 4), 256, PRE_SMEM>>>(b_r, b_z, b_h);
    rec_mma<<<BB/32, 256, REC_SMEM>>>(out);
}